// round 2
// baseline (speedup 1.0000x reference)
#include <cuda_runtime.h>
#include <cuda_bf16.h>
#include <math.h>

// Problem constants
#define T_DIM 512
#define B_DIM 256
#define E_DIM 256
#define H_DIM 256
#define G3    768   // 3*H

// Recurrence smem-cache config: first KQ_SMEM of 64 k-chunks (all 3 gates)
// live in shared memory. 3 * 18 * 256 float4 = 216 KB (+2 KB h buffer).
#define KQ_SMEM 18
#define SMEM_REC (2048 + 3 * KQ_SMEM * 256 * 16)

// ---------------------------------------------------------------------------
// Scratch (static __device__ globals — the sanctioned no-alloc workaround)
// ---------------------------------------------------------------------------
__device__ float  g_gi[(size_t)T_DIM * B_DIM * G3];   // gi[t][b][3H], ~403 MB
__device__ float4 g_wp[3 * 64 * 256];                 // packed W_hh: [gate][kq][i]
__device__ float  g_hfin[B_DIM * H_DIM];              // final hidden states

// ---------------------------------------------------------------------------
// K1: pack/transpose W_hh into [gate][kq][i] float4 layout so recurrence
// reads are fully coalesced (consecutive threads -> consecutive float4).
// g_wp[(g*64+kq)*256 + i] = W_hh[g*256+i][4kq .. 4kq+3]
// ---------------------------------------------------------------------------
__global__ void pack_whh_kernel(const float* __restrict__ whh) {
    int idx = blockIdx.x * 256 + threadIdx.x;   // 0 .. 49151
    int i   = idx & 255;                        // hidden output index
    int gkq = idx >> 8;                         // g*64 + kq
    int g   = gkq >> 6;
    int kq  = gkq & 63;
    const float* src = whh + ((size_t)(g * 256 + i)) * 256 + 4 * kq;
    g_wp[idx] = make_float4(src[0], src[1], src[2], src[3]);
}

// ---------------------------------------------------------------------------
// K2: gi = x @ W_ih^T + b_ih for all (t,b). 64x64 tile, BK=16, 256 threads,
// 4x4 micro-tile. Tiles whose 64-row batch range is fully inactive at their
// timestep are skipped (lengths sorted descending -> prefix of actives).
// ---------------------------------------------------------------------------
__global__ void __launch_bounds__(256) gi_gemm_kernel(
    const float* __restrict__ x, const float* __restrict__ wih,
    const float* __restrict__ bih, const int* __restrict__ lengths)
{
    __shared__ __align__(16) float As[16][64];
    __shared__ __align__(16) float Bs[16][64];
    __shared__ int s_nact;

    int tileN = blockIdx.x;             // 0..11  (j tile)
    int row0  = blockIdx.y << 6;        // flattened row = t*256 + b
    int t     = row0 >> 8;              // 64 rows share one t (256 % 64 == 0)
    int b0    = row0 & 255;

    if (threadIdx.x == 0) {
        // count of lengths > t (lengths sorted descending)
        int lo = 0, hi = B_DIM;
        while (lo < hi) {
            int mid = (lo + hi) >> 1;
            if (lengths[mid] > t) lo = mid + 1; else hi = mid;
        }
        s_nact = lo;
    }
    __syncthreads();
    if (b0 >= s_nact) return;           // whole tile inactive at this t

    int tid = threadIdx.x;
    int tx  = tid & 15;                 // micro col group (4 cols)
    int ty  = tid >> 4;                 // micro row group (4 rows)

    float c[4][4];
#pragma unroll
    for (int i = 0; i < 4; i++)
#pragma unroll
        for (int j = 0; j < 4; j++) c[i][j] = 0.f;

    int j0 = tileN << 6;
    int lr = tid >> 2;                  // 0..63: row within tile
    int lk = (tid & 3) << 2;            // 0,4,8,12: k offset within chunk
    const float* Ag = x   + (size_t)(row0 + lr) * 256 + lk;
    const float* Bg = wih + (size_t)(j0   + lr) * 256 + lk;

    for (int kk = 0; kk < 256; kk += 16) {
        float4 av = *reinterpret_cast<const float4*>(Ag + kk);
        float4 bv = *reinterpret_cast<const float4*>(Bg + kk);
        __syncthreads();                // previous iteration's reads done
        As[lk + 0][lr] = av.x; As[lk + 1][lr] = av.y;
        As[lk + 2][lr] = av.z; As[lk + 3][lr] = av.w;
        Bs[lk + 0][lr] = bv.x; Bs[lk + 1][lr] = bv.y;
        Bs[lk + 2][lr] = bv.z; Bs[lk + 3][lr] = bv.w;
        __syncthreads();
#pragma unroll
        for (int k = 0; k < 16; k++) {
            float4 a = *reinterpret_cast<const float4*>(&As[k][ty << 2]);
            float4 b = *reinterpret_cast<const float4*>(&Bs[k][tx << 2]);
            c[0][0] += a.x * b.x; c[0][1] += a.x * b.y; c[0][2] += a.x * b.z; c[0][3] += a.x * b.w;
            c[1][0] += a.y * b.x; c[1][1] += a.y * b.y; c[1][2] += a.y * b.z; c[1][3] += a.y * b.w;
            c[2][0] += a.z * b.x; c[2][1] += a.z * b.y; c[2][2] += a.z * b.z; c[2][3] += a.z * b.w;
            c[3][0] += a.w * b.x; c[3][1] += a.w * b.y; c[3][2] += a.w * b.z; c[3][3] += a.w * b.w;
        }
    }

    float4 bb = *reinterpret_cast<const float4*>(&bih[j0 + (tx << 2)]);
#pragma unroll
    for (int i = 0; i < 4; i++) {
        float4 o = make_float4(c[i][0] + bb.x, c[i][1] + bb.y,
                               c[i][2] + bb.z, c[i][3] + bb.w);
        *reinterpret_cast<float4*>(
            &g_gi[(size_t)(row0 + (ty << 2) + i) * G3 + j0 + (tx << 2)]) = o;
    }
}

// ---------------------------------------------------------------------------
// K3: persistent recurrence. 128 CTAs, each owns 2 adjacent batch rows
// (adjacent rows have near-equal lengths since sorted). 256 threads = one
// hidden unit each. W stream: first KQ_SMEM k-chunks (all gates) from smem,
// rest from L2 (coalesced float4). h broadcast from smem as interleaved
// float2 pairs so both rows share the same LDS. GRU pointwise with freeze
// semantics (rows with t >= len keep their hidden state).
// ---------------------------------------------------------------------------
__device__ __forceinline__ float sigm(float v) { return 1.0f / (1.0f + expf(-v)); }

__global__ void __launch_bounds__(256) gru_rec_kernel(
    const int* __restrict__ lengths, const float* __restrict__ bhh)
{
    extern __shared__ __align__(16) char dsm[];
    float2* hs = reinterpret_cast<float2*>(dsm);              // 256 float2 = 2 KB
    float4* ws = reinterpret_cast<float4*>(dsm + 2048);       // [3][KQ_SMEM][256]

    int pair = blockIdx.x;              // 0..127
    int bA = pair * 2, bB = pair * 2 + 1;
    int lenA = lengths[bA], lenB = lengths[bB];
    int lmax = max(lenA, lenB);
    int tid  = threadIdx.x;

    // Cooperative load of the smem-resident W slice
    for (int i = tid; i < 3 * KQ_SMEM * 256; i += 256) {
        int g  = i / (KQ_SMEM * 256);
        int r  = i - g * (KQ_SMEM * 256);
        int kq = r >> 8;
        int ii = r & 255;
        ws[i] = g_wp[(g * 64 + kq) * 256 + ii];
    }
    hs[tid] = make_float2(0.f, 0.f);

    float bhr = bhh[tid], bhz = bhh[256 + tid], bhn = bhh[512 + tid];
    const float* giA = g_gi + (size_t)bA * G3 + tid;
    const float* giB = g_gi + (size_t)bB * G3 + tid;
    __syncthreads();

    for (int t = 0; t < lmax; t++) {
        float ar0 = 0.f, az0 = 0.f, an0 = 0.f;
        float ar1 = 0.f, az1 = 0.f, an1 = 0.f;
        const float4* hp = reinterpret_cast<const float4*>(hs);

        // --- smem-resident chunk of W ---
#pragma unroll 6
        for (int kq = 0; kq < KQ_SMEM; kq++) {
            float4 p01 = hp[2 * kq];
            float4 p23 = hp[2 * kq + 1];
            float4 wr = ws[(0 * KQ_SMEM + kq) * 256 + tid];
            float4 wz = ws[(1 * KQ_SMEM + kq) * 256 + tid];
            float4 wn = ws[(2 * KQ_SMEM + kq) * 256 + tid];
            ar0 += wr.x * p01.x + wr.y * p01.z + wr.z * p23.x + wr.w * p23.z;
            az0 += wz.x * p01.x + wz.y * p01.z + wz.z * p23.x + wz.w * p23.z;
            an0 += wn.x * p01.x + wn.y * p01.z + wn.z * p23.x + wn.w * p23.z;
            ar1 += wr.x * p01.y + wr.y * p01.w + wr.z * p23.y + wr.w * p23.w;
            az1 += wz.x * p01.y + wz.y * p01.w + wz.z * p23.y + wz.w * p23.w;
            an1 += wn.x * p01.y + wn.y * p01.w + wn.z * p23.y + wn.w * p23.w;
        }
        // --- L2-streamed remainder of W ---
#pragma unroll 8
        for (int kq = KQ_SMEM; kq < 64; kq++) {
            float4 p01 = hp[2 * kq];
            float4 p23 = hp[2 * kq + 1];
            float4 wr = g_wp[kq * 256 + tid];
            float4 wz = g_wp[(64 + kq) * 256 + tid];
            float4 wn = g_wp[(128 + kq) * 256 + tid];
            ar0 += wr.x * p01.x + wr.y * p01.z + wr.z * p23.x + wr.w * p23.z;
            az0 += wz.x * p01.x + wz.y * p01.z + wz.z * p23.x + wz.w * p23.z;
            an0 += wn.x * p01.x + wn.y * p01.z + wn.z * p23.x + wn.w * p23.z;
            ar1 += wr.x * p01.y + wr.y * p01.w + wr.z * p23.y + wr.w * p23.w;
            az1 += wz.x * p01.y + wz.y * p01.w + wz.z * p23.y + wz.w * p23.w;
            an1 += wn.x * p01.y + wn.y * p01.w + wn.z * p23.y + wn.w * p23.w;
        }

        size_t toff = (size_t)t * (B_DIM * G3);
        float hAold = hs[tid].x, hBold = hs[tid].y;
        float hA = hAold, hB = hBold;

        if (t < lenA) {
            float ir = giA[toff], iz = giA[toff + 256], in_ = giA[toff + 512];
            float r = sigm(ir + ar0 + bhr);
            float z = sigm(iz + az0 + bhz);
            float n = tanhf(in_ + r * (an0 + bhn));
            hA = (1.f - z) * n + z * hAold;
        }
        if (t < lenB) {
            float ir = giB[toff], iz = giB[toff + 256], in_ = giB[toff + 512];
            float r = sigm(ir + ar1 + bhr);
            float z = sigm(iz + az1 + bhz);
            float n = tanhf(in_ + r * (an1 + bhn));
            hB = (1.f - z) * n + z * hBold;
        }

        __syncthreads();                 // everyone done reading hs
        hs[tid] = make_float2(hA, hB);
        __syncthreads();                 // hs updated before next matvec
    }

    g_hfin[bA * 256 + tid] = hs[tid].x;
    g_hfin[bB * 256 + tid] = hs[tid].y;
}

// ---------------------------------------------------------------------------
// K4: out[i, :] = h_final[unsorted_indices[i], :]   (output is [1, B, H] fp32)
// ---------------------------------------------------------------------------
__global__ void gather_kernel(const int* __restrict__ u, float* __restrict__ out) {
    int b = blockIdx.x;
    out[b * 256 + threadIdx.x] = g_hfin[(size_t)u[b] * 256 + threadIdx.x];
}

// ---------------------------------------------------------------------------
// Launch. Inputs (metadata order): x, W_ih, W_hh, b_ih, b_hh, lengths,
// unsorted_indices. All launches graph-capturable; no sync, no alloc.
// ---------------------------------------------------------------------------
extern "C" void kernel_launch(void* const* d_in, const int* in_sizes, int n_in,
                              void* d_out, int out_size)
{
    const float* x       = (const float*)d_in[0];
    const float* wih     = (const float*)d_in[1];
    const float* whh     = (const float*)d_in[2];
    const float* bih     = (const float*)d_in[3];
    const float* bhh     = (const float*)d_in[4];
    const int*   lengths = (const int*)d_in[5];
    const int*   uns     = (const int*)d_in[6];
    float* out = (float*)d_out;

    // Allow >48KB dynamic smem for the recurrence kernel (idempotent,
    // host-side attribute set — not a stream op, capture-safe).
    static int smem_set = 0;
    if (!smem_set) {
        cudaFuncSetAttribute(gru_rec_kernel,
                             cudaFuncAttributeMaxDynamicSharedMemorySize,
                             SMEM_REC);
        smem_set = 1;
    }

    pack_whh_kernel<<<192, 256>>>(whh);

    dim3 g2(G3 / 64, (T_DIM * B_DIM) / 64);   // (12, 2048)
    gi_gemm_kernel<<<g2, 256>>>(x, wih, bih, lengths);

    gru_rec_kernel<<<B_DIM / 2, 256, SMEM_REC>>>(lengths, bhh);

    gather_kernel<<<B_DIM, 256>>>(uns, out);
}

// round 3
// speedup vs baseline: 1.2552x; 1.2552x over previous
#include <cuda_runtime.h>
#include <cuda_fp16.h>
#include <cuda_bf16.h>
#include <math.h>

// Problem constants
#define T_DIM 512
#define B_DIM 256
#define E_DIM 256
#define H_DIM 256
#define G3    768   // 3*H

// Recurrence W layout: chunks (groups of 4 k-values) 0..KQ_SMEM-1 are fp32 and
// cached in shared memory; chunks KQ_SMEM..63 stream from L2 as fp16.
#define KQ_SMEM   18
#define KQ_STREAM (64 - KQ_SMEM)        // 46
// smem: double-buffered h (2*256*float2 = 4KB) + fp32 W cache (3*18*256*16B = 216KB)
#define SMEM_REC (4096 + 3 * KQ_SMEM * 256 * 16)

// ---------------------------------------------------------------------------
// Scratch (static __device__ globals — the sanctioned no-alloc workaround)
// ---------------------------------------------------------------------------
__device__ float  g_gi[(size_t)T_DIM * B_DIM * G3];   // gi[t][b][3H], ~403 MB
__device__ float4 g_wp [3 * KQ_SMEM   * 256];         // fp32 W chunks for smem cache
__device__ uint2  g_wph[3 * KQ_STREAM * 256];         // fp16 W chunks (half2 x2) for L2 stream
__device__ float  g_hfin[B_DIM * H_DIM];              // final hidden states

// ---------------------------------------------------------------------------
// K1: pack/transpose W_hh. For chunk kq (4 k-values) of gate g, output unit i:
//   kq <  KQ_SMEM : g_wp [(g*KQ_SMEM+kq)*256 + i]          = fp32x4
//   kq >= KQ_SMEM : g_wph[(g*KQ_STREAM+(kq-KQ_SMEM))*256+i] = half2x2
// ---------------------------------------------------------------------------
__global__ void pack_whh_kernel(const float* __restrict__ whh) {
    int idx = blockIdx.x * 256 + threadIdx.x;   // 0 .. 49151
    int i   = idx & 255;                        // hidden output index
    int gkq = idx >> 8;                         // g*64 + kq
    int g   = gkq >> 6;
    int kq  = gkq & 63;
    const float* src = whh + ((size_t)(g * 256 + i)) * 256 + 4 * kq;
    float s0 = src[0], s1 = src[1], s2 = src[2], s3 = src[3];
    if (kq < KQ_SMEM) {
        g_wp[(g * KQ_SMEM + kq) * 256 + i] = make_float4(s0, s1, s2, s3);
    } else {
        __half2 h01 = __floats2half2_rn(s0, s1);
        __half2 h23 = __floats2half2_rn(s2, s3);
        uint2 u;
        u.x = *reinterpret_cast<unsigned*>(&h01);
        u.y = *reinterpret_cast<unsigned*>(&h23);
        g_wph[(g * KQ_STREAM + (kq - KQ_SMEM)) * 256 + i] = u;
    }
}

// ---------------------------------------------------------------------------
// K2: gi = x @ W_ih^T + b_ih for all (t,b). 64x64 tile, BK=16, 256 threads,
// 4x4 micro-tile. Tiles whose 64-row batch range is fully inactive at their
// timestep are skipped (lengths sorted descending -> prefix of actives).
// ---------------------------------------------------------------------------
__global__ void __launch_bounds__(256) gi_gemm_kernel(
    const float* __restrict__ x, const float* __restrict__ wih,
    const float* __restrict__ bih, const int* __restrict__ lengths)
{
    __shared__ __align__(16) float As[16][64];
    __shared__ __align__(16) float Bs[16][64];
    __shared__ int s_nact;

    int tileN = blockIdx.x;             // 0..11  (j tile)
    int row0  = blockIdx.y << 6;        // flattened row = t*256 + b
    int t     = row0 >> 8;              // 64 rows share one t (256 % 64 == 0)
    int b0    = row0 & 255;

    if (threadIdx.x == 0) {
        int lo = 0, hi = B_DIM;
        while (lo < hi) {
            int mid = (lo + hi) >> 1;
            if (lengths[mid] > t) lo = mid + 1; else hi = mid;
        }
        s_nact = lo;
    }
    __syncthreads();
    if (b0 >= s_nact) return;           // whole tile inactive at this t

    int tid = threadIdx.x;
    int tx  = tid & 15;
    int ty  = tid >> 4;

    float c[4][4];
#pragma unroll
    for (int i = 0; i < 4; i++)
#pragma unroll
        for (int j = 0; j < 4; j++) c[i][j] = 0.f;

    int j0 = tileN << 6;
    int lr = tid >> 2;
    int lk = (tid & 3) << 2;
    const float* Ag = x   + (size_t)(row0 + lr) * 256 + lk;
    const float* Bg = wih + (size_t)(j0   + lr) * 256 + lk;

    for (int kk = 0; kk < 256; kk += 16) {
        float4 av = *reinterpret_cast<const float4*>(Ag + kk);
        float4 bv = *reinterpret_cast<const float4*>(Bg + kk);
        __syncthreads();
        As[lk + 0][lr] = av.x; As[lk + 1][lr] = av.y;
        As[lk + 2][lr] = av.z; As[lk + 3][lr] = av.w;
        Bs[lk + 0][lr] = bv.x; Bs[lk + 1][lr] = bv.y;
        Bs[lk + 2][lr] = bv.z; Bs[lk + 3][lr] = bv.w;
        __syncthreads();
#pragma unroll
        for (int k = 0; k < 16; k++) {
            float4 a = *reinterpret_cast<const float4*>(&As[k][ty << 2]);
            float4 b = *reinterpret_cast<const float4*>(&Bs[k][tx << 2]);
            c[0][0] += a.x * b.x; c[0][1] += a.x * b.y; c[0][2] += a.x * b.z; c[0][3] += a.x * b.w;
            c[1][0] += a.y * b.x; c[1][1] += a.y * b.y; c[1][2] += a.y * b.z; c[1][3] += a.y * b.w;
            c[2][0] += a.z * b.x; c[2][1] += a.z * b.y; c[2][2] += a.z * b.z; c[2][3] += a.z * b.w;
            c[3][0] += a.w * b.x; c[3][1] += a.w * b.y; c[3][2] += a.w * b.z; c[3][3] += a.w * b.w;
        }
    }

    float4 bb = *reinterpret_cast<const float4*>(&bih[j0 + (tx << 2)]);
#pragma unroll
    for (int i = 0; i < 4; i++) {
        float4 o = make_float4(c[i][0] + bb.x, c[i][1] + bb.y,
                               c[i][2] + bb.z, c[i][3] + bb.w);
        *reinterpret_cast<float4*>(
            &g_gi[(size_t)(row0 + (ty << 2) + i) * G3 + j0 + (tx << 2)]) = o;
    }
}

// ---------------------------------------------------------------------------
// K3: persistent recurrence. 128 CTAs x 2 adjacent batch rows, 256 threads =
// one hidden unit each. W: KQ_SMEM fp32 chunks from smem + KQ_STREAM fp16
// chunks from L2. h double-buffered in smem (ONE barrier/step). gi[t]
// prefetched before the matvec so its latency hides under the FFMA stream.
// ---------------------------------------------------------------------------
__device__ __forceinline__ float fast_sigm(float v) {
    return __fdividef(1.0f, 1.0f + __expf(-v));
}
__device__ __forceinline__ float fast_tanh(float v) {
    float e = __expf(2.0f * v);
    return __fdividef(e - 1.0f, e + 1.0f);
}

__global__ void __launch_bounds__(256) gru_rec_kernel(
    const int* __restrict__ lengths, const float* __restrict__ bhh)
{
    extern __shared__ __align__(16) char dsm[];
    float2* hbuf = reinterpret_cast<float2*>(dsm);            // [2][256] float2
    float4* ws   = reinterpret_cast<float4*>(dsm + 4096);     // [3][KQ_SMEM][256]

    int pair = blockIdx.x;              // 0..127
    int bA = pair * 2, bB = pair * 2 + 1;
    int lenA = lengths[bA], lenB = lengths[bB];
    int lmax = max(lenA, lenB);
    int tid  = threadIdx.x;

    // Cooperative load of the fp32 smem-resident W slice
    for (int i = tid; i < 3 * KQ_SMEM * 256; i += 256)
        ws[i] = g_wp[i];
    hbuf[tid]       = make_float2(0.f, 0.f);
    hbuf[256 + tid] = make_float2(0.f, 0.f);

    float bhr = bhh[tid], bhz = bhh[256 + tid], bhn = bhh[512 + tid];
    const float* giA = g_gi + (size_t)bA * G3 + tid;
    const float* giB = g_gi + (size_t)bB * G3 + tid;
    __syncthreads();

    int p = 0;
    for (int t = 0; t < lmax; t++) {
        // ---- prefetch gi[t] (latency hides under the matvec) ----
        size_t toff = (size_t)t * (B_DIM * G3);
        bool actA = t < lenA, actB = t < lenB;
        float irA = 0.f, izA = 0.f, inA = 0.f;
        float irB = 0.f, izB = 0.f, inB = 0.f;
        if (actA) { irA = giA[toff]; izA = giA[toff + 256]; inA = giA[toff + 512]; }
        if (actB) { irB = giB[toff]; izB = giB[toff + 256]; inB = giB[toff + 512]; }

        float ar0 = 0.f, az0 = 0.f, an0 = 0.f;
        float ar1 = 0.f, az1 = 0.f, an1 = 0.f;
        const float4* hp = reinterpret_cast<const float4*>(hbuf + 256 * p);

        // ---- fp32 smem-resident chunk of W ----
#pragma unroll 6
        for (int kq = 0; kq < KQ_SMEM; kq++) {
            float4 p01 = hp[2 * kq];
            float4 p23 = hp[2 * kq + 1];
            float4 wr = ws[(0 * KQ_SMEM + kq) * 256 + tid];
            float4 wz = ws[(1 * KQ_SMEM + kq) * 256 + tid];
            float4 wn = ws[(2 * KQ_SMEM + kq) * 256 + tid];
            ar0 += wr.x * p01.x + wr.y * p01.z + wr.z * p23.x + wr.w * p23.z;
            az0 += wz.x * p01.x + wz.y * p01.z + wz.z * p23.x + wz.w * p23.z;
            an0 += wn.x * p01.x + wn.y * p01.z + wn.z * p23.x + wn.w * p23.z;
            ar1 += wr.x * p01.y + wr.y * p01.w + wr.z * p23.y + wr.w * p23.w;
            az1 += wz.x * p01.y + wz.y * p01.w + wz.z * p23.y + wz.w * p23.w;
            an1 += wn.x * p01.y + wn.y * p01.w + wn.z * p23.y + wn.w * p23.w;
        }
        // ---- fp16 L2-streamed remainder of W ----
#pragma unroll 4
        for (int kqs = 0; kqs < KQ_STREAM; kqs++) {
            int kq = KQ_SMEM + kqs;
            float4 p01 = hp[2 * kq];
            float4 p23 = hp[2 * kq + 1];
            uint2 ur = g_wph[(0 * KQ_STREAM + kqs) * 256 + tid];
            uint2 uz = g_wph[(1 * KQ_STREAM + kqs) * 256 + tid];
            uint2 un = g_wph[(2 * KQ_STREAM + kqs) * 256 + tid];
            float2 rlo = __half22float2(*reinterpret_cast<__half2*>(&ur.x));
            float2 rhi = __half22float2(*reinterpret_cast<__half2*>(&ur.y));
            float2 zlo = __half22float2(*reinterpret_cast<__half2*>(&uz.x));
            float2 zhi = __half22float2(*reinterpret_cast<__half2*>(&uz.y));
            float2 nlo = __half22float2(*reinterpret_cast<__half2*>(&un.x));
            float2 nhi = __half22float2(*reinterpret_cast<__half2*>(&un.y));
            ar0 += rlo.x * p01.x + rlo.y * p01.z + rhi.x * p23.x + rhi.y * p23.z;
            az0 += zlo.x * p01.x + zlo.y * p01.z + zhi.x * p23.x + zhi.y * p23.z;
            an0 += nlo.x * p01.x + nlo.y * p01.z + nhi.x * p23.x + nhi.y * p23.z;
            ar1 += rlo.x * p01.y + rlo.y * p01.w + rhi.x * p23.y + rhi.y * p23.w;
            az1 += zlo.x * p01.y + zlo.y * p01.w + zhi.x * p23.y + zhi.y * p23.w;
            an1 += nlo.x * p01.y + nlo.y * p01.w + nhi.x * p23.y + nhi.y * p23.w;
        }

        float2 hold = hbuf[256 * p + tid];
        float hA = hold.x, hB = hold.y;

        if (actA) {
            float r = fast_sigm(irA + ar0 + bhr);
            float z = fast_sigm(izA + az0 + bhz);
            float n = fast_tanh(inA + r * (an0 + bhn));
            hA = (1.f - z) * n + z * hA;
        }
        if (actB) {
            float r = fast_sigm(irB + ar1 + bhr);
            float z = fast_sigm(izB + az1 + bhz);
            float n = fast_tanh(inB + r * (an1 + bhn));
            hB = (1.f - z) * n + z * hB;
        }

        hbuf[256 * (p ^ 1) + tid] = make_float2(hA, hB);
        __syncthreads();                 // single barrier: publish h(t+1)
        p ^= 1;
    }

    float2 hf = hbuf[256 * p + tid];
    g_hfin[bA * 256 + tid] = hf.x;
    g_hfin[bB * 256 + tid] = hf.y;
}

// ---------------------------------------------------------------------------
// K4: out[i, :] = h_final[unsorted_indices[i], :]   (output is [1, B, H] fp32)
// ---------------------------------------------------------------------------
__global__ void gather_kernel(const int* __restrict__ u, float* __restrict__ out) {
    int b = blockIdx.x;
    out[b * 256 + threadIdx.x] = g_hfin[(size_t)u[b] * 256 + threadIdx.x];
}

// ---------------------------------------------------------------------------
// Launch. Inputs (metadata order): x, W_ih, W_hh, b_ih, b_hh, lengths,
// unsorted_indices. All launches graph-capturable; no sync, no alloc.
// ---------------------------------------------------------------------------
extern "C" void kernel_launch(void* const* d_in, const int* in_sizes, int n_in,
                              void* d_out, int out_size)
{
    const float* x       = (const float*)d_in[0];
    const float* wih     = (const float*)d_in[1];
    const float* whh     = (const float*)d_in[2];
    const float* bih     = (const float*)d_in[3];
    const float* bhh     = (const float*)d_in[4];
    const int*   lengths = (const int*)d_in[5];
    const int*   uns     = (const int*)d_in[6];
    float* out = (float*)d_out;

    static int smem_set = 0;
    if (!smem_set) {
        cudaFuncSetAttribute(gru_rec_kernel,
                             cudaFuncAttributeMaxDynamicSharedMemorySize,
                             SMEM_REC);
        smem_set = 1;
    }

    pack_whh_kernel<<<192, 256>>>(whh);

    dim3 g2(G3 / 64, (T_DIM * B_DIM) / 64);   // (12, 2048)
    gi_gemm_kernel<<<g2, 256>>>(x, wih, bih, lengths);

    gru_rec_kernel<<<B_DIM / 2, 256, SMEM_REC>>>(lengths, bhh);

    gather_kernel<<<B_DIM, 256>>>(uns, out);
}